// round 5
// baseline (speedup 1.0000x reference)
#include <cuda_runtime.h>
#include <math.h>

// Problem constants
#define HW      25600      // H*W = 160*160
#define TP      128        // pixels per tile
#define TILES   200        // HW / TP
#define BB      8          // batch
#define NT      512        // threads per block
#define EPSV    1e-6f
#define RCH     8          // reduce chunks
#define TPC     (TILES/RCH) // tiles per chunk = 25

typedef unsigned long long u64;

// Scratch (no allocations allowed): per-tile partials + reduced stats.
// Layout of the 576 entries: [0..511] attn[p][m][c] (e = p*64+m*8+c), [512..575] ksum[p][m]
__device__ float g_part[BB * TILES * 576];
__device__ float g_part2[BB * RCH * 576];
__device__ float g_stats[BB * 576];

// ---------- packed f32x2 helpers (sm_103a) ----------
__device__ __forceinline__ u64 pk2(float a, float b) {
    u64 r; asm("mov.b64 %0, {%1, %2};" : "=l"(r) : "f"(a), "f"(b)); return r;
}
__device__ __forceinline__ void upk2(u64 v, float& a, float& b) {
    asm("mov.b64 {%0, %1}, %2;" : "=f"(a), "=f"(b) : "l"(v));
}
__device__ __forceinline__ u64 f2fma(u64 a, u64 b, u64 c) {
    u64 d; asm("fma.rn.f32x2 %0, %1, %2, %3;" : "=l"(d) : "l"(a), "l"(b), "l"(c)); return d;
}
__device__ __forceinline__ u64 f2mul(u64 a, u64 b) {
    u64 d; asm("mul.rn.f32x2 %0, %1, %2;" : "=l"(d) : "l"(a), "l"(b)); return d;
}
__device__ __forceinline__ u64 f2add(u64 a, u64 b) {
    u64 d; asm("add.rn.f32x2 %0, %1, %2;" : "=l"(d) : "l"(a), "l"(b)); return d;
}

// Fast softplus via MUFU ex2/lg2: max(x,0) + ln(1 + 2^(-|x|*log2e))
// abs err ~1e-7 -> well within 1e-3 rel-err gate.
__device__ __forceinline__ float softplusf(float x) {
    const float LOG2E = 1.4426950408889634f;
    const float LN2   = 0.6931471805599453f;
    float t = -fabsf(x) * LOG2E;
    float e; asm("ex2.approx.f32 %0, %1;" : "=f"(e) : "f"(t));   // 2^t = exp(-|x|)
    float l; asm("lg2.approx.f32 %0, %1;" : "=f"(l) : "f"(1.0f + e));
    return fmaxf(x, 0.0f) + l * LN2;
}

// =====================================================================
// Pass 1: k = softplus(wk@low + bk), v = wv@low + bv   (128 out ch)
//         per-tile partial attn[p][m][c] = sum_n k[m,n]*v[c,n]
//         per-tile partial ksum[p][m]    = sum_n k[m,n]
// =====================================================================
// smem: Wpk  u64 [64][128]  (packed {w,w})  : 65536 B
//       Xs   f32 [64][128]                  : 32768 B  @ 65536
//       KVs  f32 [128][132] (pad for banks) : 67584 B  @ 98304
// total 165888 B
__global__ void __launch_bounds__(NT, 1)
pass1_kernel(const float* __restrict__ low,
             const float* __restrict__ wk, const float* __restrict__ bk,
             const float* __restrict__ wv, const float* __restrict__ bv)
{
    extern __shared__ __align__(16) char smem[];
    u64*   Wpk = (u64*)smem;                     // [c][oc] oc<64: k, else v
    float* Xs  = (float*)(smem + 65536);         // [c][n]
    float* KVs = (float*)(smem + 98304);         // [ch][n] stride 132; ch<64 k, ch>=64 v

    const int tid = threadIdx.x;
    const int b   = blockIdx.y;
    const int px0 = blockIdx.x * TP;

    // Stage packed weights [c][oc]
    for (int i = tid; i < 64 * 128; i += NT) {
        int c = i >> 7, oc = i & 127;
        float w = (oc < 64) ? wk[oc * 64 + c] : wv[(oc - 64) * 64 + c];
        Wpk[i] = pk2(w, w);
    }
    // Stage input tile [c][n] (coalesced over n)
    const float* lowb = low + (size_t)b * 64 * HW + px0;
    for (int i = tid; i < 64 * 128; i += NT) {
        int c = i >> 7, n = i & 127;
        Xs[i] = lowb[c * HW + n];
    }
    __syncthreads();

    // GEMM: 512 threads = 32 ch-groups(4ch) x 16 px-groups(8px: two chunks of 4)
    const int cg = tid >> 4;           // 0..31
    const int pg = tid & 15;           // 0..15
    const int co = cg * 4;
    const int j0 = pg * 4;
    const int j1 = 64 + pg * 4;

    u64 acc[4][4];
    #pragma unroll
    for (int i = 0; i < 4; i++) {
        int oc = co + i;
        float bi = (oc < 64) ? bk[oc] : bv[oc - 64];
        u64 bp = pk2(bi, bi);
        acc[i][0] = bp; acc[i][1] = bp; acc[i][2] = bp; acc[i][3] = bp;
    }

    #pragma unroll 8
    for (int c = 0; c < 64; c++) {
        ulonglong2 w01 = *(const ulonglong2*)&Wpk[c * 128 + co];
        ulonglong2 w23 = *(const ulonglong2*)&Wpk[c * 128 + co + 2];
        ulonglong2 x0  = *(const ulonglong2*)&Xs[c * 128 + j0];
        ulonglong2 x1  = *(const ulonglong2*)&Xs[c * 128 + j1];
        u64 w[4] = {w01.x, w01.y, w23.x, w23.y};
        #pragma unroll
        for (int i = 0; i < 4; i++) {
            acc[i][0] = f2fma(w[i], x0.x, acc[i][0]);
            acc[i][1] = f2fma(w[i], x0.y, acc[i][1]);
            acc[i][2] = f2fma(w[i], x1.x, acc[i][2]);
            acc[i][3] = f2fma(w[i], x1.y, acc[i][3]);
        }
    }

    // Epilogue: softplus on k channels, write [ch][n]
    const bool isk = (co < 64);
    #pragma unroll
    for (int i = 0; i < 4; i++) {
        int oc = co + i;
        float v0,v1,v2,v3,v4,v5,v6,v7;
        upk2(acc[i][0], v0, v1); upk2(acc[i][1], v2, v3);
        upk2(acc[i][2], v4, v5); upk2(acc[i][3], v6, v7);
        if (isk) {
            v0 = softplusf(v0); v1 = softplusf(v1); v2 = softplusf(v2); v3 = softplusf(v3);
            v4 = softplusf(v4); v5 = softplusf(v5); v6 = softplusf(v6); v7 = softplusf(v7);
        }
        *(float4*)&KVs[oc * 132 + j0] = make_float4(v0, v1, v2, v3);
        *(float4*)&KVs[oc * 132 + j1] = make_float4(v4, v5, v6, v7);
    }
    __syncthreads();

    // Per-tile attn partials: one entry per thread (512 entries)
    // attn[p][m][c] = sum_n k[p*8+m][n] * v[p*8+c][n];  v rows live at +64.
    // LDS.128 (4 floats / 2 pairs per load) to halve LDS issue count.
    {
        const int e  = tid;
        const int p  = e >> 6;
        const int m  = (e >> 3) & 7;
        const int cx = e & 7;
        const float* rk = &KVs[(p * 8 + m)        * 132];
        const float* rv = &KVs[(64 + p * 8 + cx)  * 132];
        u64 s0 = 0ull, s1 = 0ull;
        #pragma unroll 8
        for (int n4 = 0; n4 < 32; n4++) {
            ulonglong2 kk = *(const ulonglong2*)&rk[4 * n4];
            ulonglong2 vv = *(const ulonglong2*)&rv[4 * n4];
            s0 = f2fma(kk.x, vv.x, s0);
            s1 = f2fma(kk.y, vv.y, s1);
        }
        u64 s = f2add(s0, s1);
        float a0, a1; upk2(s, a0, a1);
        g_part[(size_t)(b * TILES + blockIdx.x) * 576 + e] = a0 + a1;
    }
    // ksum partials (k rows are 0..63)
    if (tid < 64) {
        const float* rk = &KVs[tid * 132];
        u64 s0 = 0ull, s1 = 0ull;
        #pragma unroll 8
        for (int n4 = 0; n4 < 32; n4++) {
            ulonglong2 kk = *(const ulonglong2*)&rk[4 * n4];
            s0 = f2add(s0, kk.x);
            s1 = f2add(s1, kk.y);
        }
        u64 s = f2add(s0, s1);
        float a0, a1; upk2(s, a0, a1);
        g_part[(size_t)(b * TILES + blockIdx.x) * 576 + 512 + tid] = a0 + a1;
    }
}

// =====================================================================
// Two-stage tile reduce (deterministic, fixed order, no float atomics).
// Stage 1: 64 CTAs, each sums 25 tiles. Stage 2: 8 CTAs fold 8 chunks,
// ksum gets +EPS.
// =====================================================================
__global__ void reduce1_kernel()
{
    const int b  = blockIdx.y;
    const int ch = blockIdx.x;       // 0..RCH-1
    const int e  = threadIdx.x;      // 0..575
    float s = 0.0f;
    const float* p = &g_part[((size_t)b * TILES + ch * TPC) * 576 + e];
    #pragma unroll 5
    for (int t = 0; t < TPC; t++) s += p[(size_t)t * 576];
    g_part2[(b * RCH + ch) * 576 + e] = s;
}

__global__ void reduce2_kernel()
{
    const int b = blockIdx.x;
    const int e = threadIdx.x;   // 0..575
    float s = 0.0f;
    const float* p = &g_part2[(size_t)(b * RCH) * 576 + e];
    #pragma unroll
    for (int c = 0; c < RCH; c++) s += p[(size_t)c * 576];
    g_stats[b * 576 + e] = (e < 512) ? s : (s + EPSV);
}

// =====================================================================
// Pass 2: q = softplus(Wq@{high|low} + bq)  (heads 0-3 from high, 4-7 low)
//         norm[n] = 1 / sum_m q[n,m]*(ksum[m]+eps)
//         O[p*8+c][n] = norm[n] * sum_m q[n,m]*attn[p][m][c]
//         out = wo @ O + bo
// =====================================================================
// smem layout (bytes):
//   Wq  u64[64][64]            32768 @ 0
//   Wo  u64[64][64]            32768 @ 32768
//   Asp u64[512]                4096 @ 65536   (packed attn {a,a})
//   Ksp u64[64]                  512 @ 69632   (packed ksum+eps)
//   Hs  f32[64][128]           32768 @ 70144
//   Ls  f32[64][128]           32768 @ 102912
//   Qs  f32[64][132]           33792 @ 135680
//   Os  f32[64][132]           33792 @ 169472
//   Ns  f32[8][132]             4224 @ 203264
// total 207488 B
__global__ void __launch_bounds__(NT, 1)
pass2_kernel(const float* __restrict__ high, const float* __restrict__ low,
             const float* __restrict__ wqh, const float* __restrict__ bqh,
             const float* __restrict__ wql, const float* __restrict__ bql,
             const float* __restrict__ wo,  const float* __restrict__ bo,
             float* __restrict__ out)
{
    extern __shared__ __align__(16) char smem[];
    u64*   Wq  = (u64*)smem;
    u64*   Wo  = (u64*)(smem + 32768);
    u64*   Asp = (u64*)(smem + 65536);
    u64*   Ksp = (u64*)(smem + 69632);
    float* Hs  = (float*)(smem + 70144);
    float* Ls  = (float*)(smem + 102912);
    float* Qs  = (float*)(smem + 135680);
    float* Os  = (float*)(smem + 169472);
    float* Ns  = (float*)(smem + 203264);

    const int tid = threadIdx.x;
    const int b   = blockIdx.y;
    const int px0 = blockIdx.x * TP;

    // Stage weights packed [c][oc]
    for (int i = tid; i < 4096; i += NT) {
        int c = i >> 6, oc = i & 63;
        float wq = (oc < 32) ? wqh[oc * 64 + c] : wql[(oc - 32) * 64 + c];
        Wq[i] = pk2(wq, wq);
        float w2 = wo[oc * 64 + c];   // Wo[c][o] = wo[o][c]
        Wo[i] = pk2(w2, w2);
    }
    // Stage input tiles
    for (int i = tid; i < 8192; i += NT) {
        int c = i >> 7, n = i & 127;
        size_t base = (size_t)(b * 64 + c) * HW + px0 + n;
        Hs[i] = high[base];
        Ls[i] = low[base];
    }
    // Stage attn / ksum+eps (packed broadcasts)
    { float a = g_stats[b * 576 + tid];                Asp[tid] = pk2(a, a); }
    if (tid < 64) { float k = g_stats[b * 576 + 512 + tid]; Ksp[tid] = pk2(k, k); }
    __syncthreads();

    // GEMM assignment: 16 ch-groups(4ch) x 32 px-groups(4px)
    const int cg = tid >> 5;        // 0..15
    const int pg = tid & 31;        // 0..31
    const int co = cg * 4;
    const int j0 = pg * 4;

    // ---- GEMM1: q ----
    {
        const float* src = (co < 32) ? Hs : Ls;
        u64 acc[4][2];
        #pragma unroll
        for (int i = 0; i < 4; i++) {
            int oc = co + i;
            float bi = (oc < 32) ? bqh[oc] : bql[oc - 32];
            u64 bp = pk2(bi, bi);
            acc[i][0] = bp; acc[i][1] = bp;
        }
        #pragma unroll 8
        for (int c = 0; c < 64; c++) {
            ulonglong2 w01 = *(const ulonglong2*)&Wq[c * 64 + co];
            ulonglong2 w23 = *(const ulonglong2*)&Wq[c * 64 + co + 2];
            ulonglong2 x   = *(const ulonglong2*)&src[c * 128 + j0];
            u64 w[4] = {w01.x, w01.y, w23.x, w23.y};
            #pragma unroll
            for (int i = 0; i < 4; i++) {
                acc[i][0] = f2fma(w[i], x.x, acc[i][0]);
                acc[i][1] = f2fma(w[i], x.y, acc[i][1]);
            }
        }
        #pragma unroll
        for (int i = 0; i < 4; i++) {
            float v0,v1,v2,v3;
            upk2(acc[i][0], v0, v1); upk2(acc[i][1], v2, v3);
            v0 = softplusf(v0); v1 = softplusf(v1);
            v2 = softplusf(v2); v3 = softplusf(v3);
            *(float4*)&Qs[(co + i) * 132 + j0] = make_float4(v0, v1, v2, v3);
        }
    }
    __syncthreads();

    // ---- norm: 512 entries = 8 heads x 64 pixel-pairs ----
    {
        const int p  = tid >> 6;
        const int n2 = tid & 63;
        u64 s = 0ull;
        #pragma unroll
        for (int m = 0; m < 8; m++)
            s = f2fma(*(const u64*)&Qs[(p * 8 + m) * 132 + 2 * n2], Ksp[p * 8 + m], s);
        float d0, d1; upk2(s, d0, d1);
        *(u64*)&Ns[p * 132 + 2 * n2] = pk2(1.0f / d0, 1.0f / d1);
    }
    __syncthreads();

    // ---- stage A: O[ch][n] ----
    #pragma unroll
    for (int it = 0; it < 8; it++) {
        int idx = it * NT + tid;          // 0..4095 = 64 ch x 64 pairs
        int ch = idx >> 6, n2 = idx & 63;
        int p = ch >> 3, cc = ch & 7;
        u64 s = 0ull;
        #pragma unroll
        for (int m = 0; m < 8; m++)
            s = f2fma(*(const u64*)&Qs[(p * 8 + m) * 132 + 2 * n2],
                      Asp[p * 64 + m * 8 + cc], s);
        s = f2mul(s, *(const u64*)&Ns[p * 132 + 2 * n2]);
        *(u64*)&Os[ch * 132 + 2 * n2] = s;
    }
    __syncthreads();

    // ---- GEMM3: wo ----
    {
        u64 acc[4][2];
        #pragma unroll
        for (int i = 0; i < 4; i++) {
            float bi = bo[co + i];
            u64 bp = pk2(bi, bi);
            acc[i][0] = bp; acc[i][1] = bp;
        }
        #pragma unroll 8
        for (int c = 0; c < 64; c++) {
            ulonglong2 w01 = *(const ulonglong2*)&Wo[c * 64 + co];
            ulonglong2 w23 = *(const ulonglong2*)&Wo[c * 64 + co + 2];
            ulonglong2 x   = *(const ulonglong2*)&Os[c * 132 + j0];
            u64 w[4] = {w01.x, w01.y, w23.x, w23.y};
            #pragma unroll
            for (int i = 0; i < 4; i++) {
                acc[i][0] = f2fma(w[i], x.x, acc[i][0]);
                acc[i][1] = f2fma(w[i], x.y, acc[i][1]);
            }
        }
        float* dst = out + (size_t)b * 64 * HW + px0;
        #pragma unroll
        for (int i = 0; i < 4; i++) {
            float v0,v1,v2,v3;
            upk2(acc[i][0], v0, v1); upk2(acc[i][1], v2, v3);
            *(float4*)&dst[(size_t)(co + i) * HW + j0] = make_float4(v0, v1, v2, v3);
        }
    }
}

// =====================================================================
extern "C" void kernel_launch(void* const* d_in, const int* in_sizes, int n_in,
                              void* d_out, int out_size)
{
    const float* high = (const float*)d_in[0];
    const float* low  = (const float*)d_in[1];
    const float* wqh  = (const float*)d_in[2];
    const float* bqh  = (const float*)d_in[3];
    const float* wql  = (const float*)d_in[4];
    const float* bql  = (const float*)d_in[5];
    const float* wk   = (const float*)d_in[6];
    const float* bk   = (const float*)d_in[7];
    const float* wv   = (const float*)d_in[8];
    const float* bv   = (const float*)d_in[9];
    const float* wo   = (const float*)d_in[10];
    const float* bo   = (const float*)d_in[11];
    float* out = (float*)d_out;

    cudaFuncSetAttribute(pass1_kernel, cudaFuncAttributeMaxDynamicSharedMemorySize, 165888);
    cudaFuncSetAttribute(pass2_kernel, cudaFuncAttributeMaxDynamicSharedMemorySize, 207488);

    pass1_kernel<<<dim3(TILES, BB), NT, 165888>>>(low, wk, bk, wv, bv);
    reduce1_kernel<<<dim3(RCH, BB), 576>>>();
    reduce2_kernel<<<BB, 576>>>();
    pass2_kernel<<<dim3(TILES, BB), NT, 207488>>>(high, low, wqh, bqh, wql, bql, wo, bo, out);
}

// round 8
// speedup vs baseline: 1.3728x; 1.3728x over previous
#include <cuda_runtime.h>
#include <math.h>

// Problem constants
#define HW      25600      // H*W = 160*160
#define BB      8          // batch
#define NT      512        // threads per block
#define EPSV    1e-6f
// pass1 tiling
#define TP1     64
#define TILES1  400
// pass2 tiling
#define TP2     128
#define TILES2  200
// reduce
#define RCH     16
#define TPC     (TILES1/RCH)   // 25

typedef unsigned long long u64;

// Scratch: per-tile partials + reduced stats.
// 576 entries: [0..511] attn[p][m][c] (e = p*64+m*8+c), [512..575] ksum[p][m]
__device__ float g_part[BB * TILES1 * 576];
__device__ float g_part2[BB * RCH * 576];
__device__ float g_stats[BB * 576];

// ---------- packed f32x2 helpers (sm_103a) ----------
__device__ __forceinline__ u64 pk2(float a, float b) {
    u64 r; asm("mov.b64 %0, {%1, %2};" : "=l"(r) : "f"(a), "f"(b)); return r;
}
__device__ __forceinline__ void upk2(u64 v, float& a, float& b) {
    asm("mov.b64 {%0, %1}, %2;" : "=f"(a), "=f"(b) : "l"(v));
}
__device__ __forceinline__ u64 f2fma(u64 a, u64 b, u64 c) {
    u64 d; asm("fma.rn.f32x2 %0, %1, %2, %3;" : "=l"(d) : "l"(a), "l"(b), "l"(c)); return d;
}
__device__ __forceinline__ u64 f2mul(u64 a, u64 b) {
    u64 d; asm("mul.rn.f32x2 %0, %1, %2;" : "=l"(d) : "l"(a), "l"(b)); return d;
}
__device__ __forceinline__ u64 f2add(u64 a, u64 b) {
    u64 d; asm("add.rn.f32x2 %0, %1, %2;" : "=l"(d) : "l"(a), "l"(b)); return d;
}
// Fast softplus via MUFU ex2/lg2 (abs err ~1e-7)
__device__ __forceinline__ float softplusf(float x) {
    const float LOG2E = 1.4426950408889634f;
    const float LN2   = 0.6931471805599453f;
    float t = -fabsf(x) * LOG2E;
    float e; asm("ex2.approx.f32 %0, %1;" : "=f"(e) : "f"(t));
    float l; asm("lg2.approx.f32 %0, %1;" : "=f"(l) : "f"(1.0f + e));
    return fmaxf(x, 0.0f) + l * LN2;
}

// =====================================================================
// Pass 1 (TP1=64 px/tile): k = softplus(wk@low+bk), v = wv@low+bv
//   per-tile partials: attn[p][m][c] = sum_n k*v ; ksum[p][m] = sum_n k
// smem: Wpk u64[64][128] @0 (65536) + Xs f32[64][64] @65536 (16384) = 81920
//       KVs f32[128][68] @0 (34816)  -- ALIASES Wpk after GEMM (acc in regs)
// =====================================================================
__global__ void __launch_bounds__(NT, 2)
pass1_kernel(const float* __restrict__ low,
             const float* __restrict__ wk, const float* __restrict__ bk,
             const float* __restrict__ wv, const float* __restrict__ bv)
{
    extern __shared__ __align__(16) char smem[];
    u64*   Wpk = (u64*)smem;                 // [c][oc] dup-packed {w,w}
    float* Xs  = (float*)(smem + 65536);     // [c][n]
    float* KVs = (float*)smem;               // [ch][n] stride 68 (alias)

    const int tid = threadIdx.x;
    const int b   = blockIdx.y;
    const int px0 = blockIdx.x * TP1;

    // Stage weights: i = cH*1024 + oc*8 + cL  (32B gmem sectors per oc)
    for (int i = tid; i < 8192; i += NT) {
        int oc = (i >> 3) & 127;
        int c  = (i & 7) | ((i >> 10) << 3);
        float w = (oc < 64) ? wk[oc * 64 + c] : wv[(oc - 64) * 64 + c];
        Wpk[c * 128 + oc] = pk2(w, w);
    }
    // Stage input tile [c][n]
    const float* lowb = low + (size_t)b * 64 * HW + px0;
    for (int i = tid; i < 4096; i += NT) {
        int c = i >> 6, n = i & 63;
        Xs[c * 64 + n] = lowb[c * HW + n];
    }
    __syncthreads();

    // GEMM: 512 thr = 32 ch-groups(4ch) x 16 px-groups(4px)
    const int cg = tid >> 4;         // 0..31
    const int pg = tid & 15;         // 0..15
    const int co = cg * 4;
    const int j0 = pg * 4;

    u64 acc[4][2];
    #pragma unroll
    for (int i = 0; i < 4; i++) {
        int oc = co + i;
        float bi = (oc < 64) ? bk[oc] : bv[oc - 64];
        u64 bp = pk2(bi, bi);
        acc[i][0] = bp; acc[i][1] = bp;
    }

    #pragma unroll 8
    for (int c = 0; c < 64; c++) {
        ulonglong2 w01 = *(const ulonglong2*)&Wpk[c * 128 + co];
        ulonglong2 w23 = *(const ulonglong2*)&Wpk[c * 128 + co + 2];
        ulonglong2 x   = *(const ulonglong2*)&Xs[c * 64 + j0];
        u64 w[4] = {w01.x, w01.y, w23.x, w23.y};
        #pragma unroll
        for (int i = 0; i < 4; i++) {
            acc[i][0] = f2fma(w[i], x.x, acc[i][0]);
            acc[i][1] = f2fma(w[i], x.y, acc[i][1]);
        }
    }

    __syncthreads();   // all reads of Wpk/Xs complete; accs live in regs; safe to alias

    // Epilogue AFTER barrier (keeps peak live regs low): softplus on k channels
    const bool isk = (co < 64);
    #pragma unroll
    for (int i = 0; i < 4; i++) {
        float v0, v1, v2, v3;
        upk2(acc[i][0], v0, v1);
        upk2(acc[i][1], v2, v3);
        if (isk) {
            v0 = softplusf(v0); v1 = softplusf(v1);
            v2 = softplusf(v2); v3 = softplusf(v3);
        }
        *(float4*)&KVs[(co + i) * 68 + j0] = make_float4(v0, v1, v2, v3);
    }
    __syncthreads();

    // attn partials: one (p,m,c) entry per thread
    {
        const int e  = tid;
        const int p  = e >> 6;
        const int m  = (e >> 3) & 7;
        const int cx = e & 7;
        const float* rk = &KVs[(p * 8 + m)       * 68];
        const float* rv = &KVs[(64 + p * 8 + cx) * 68];
        u64 s0 = 0ull, s1 = 0ull;
        #pragma unroll
        for (int n4 = 0; n4 < 16; n4++) {
            ulonglong2 kk = *(const ulonglong2*)&rk[4 * n4];
            ulonglong2 vv = *(const ulonglong2*)&rv[4 * n4];
            s0 = f2fma(kk.x, vv.x, s0);
            s1 = f2fma(kk.y, vv.y, s1);
        }
        u64 s = f2add(s0, s1);
        float a0, a1; upk2(s, a0, a1);
        g_part[(size_t)(b * TILES1 + blockIdx.x) * 576 + e] = a0 + a1;
    }
    // ksum partials
    if (tid < 64) {
        const float* rk = &KVs[tid * 68];
        u64 s0 = 0ull, s1 = 0ull;
        #pragma unroll
        for (int n4 = 0; n4 < 16; n4++) {
            ulonglong2 kk = *(const ulonglong2*)&rk[4 * n4];
            s0 = f2add(s0, kk.x);
            s1 = f2add(s1, kk.y);
        }
        u64 s = f2add(s0, s1);
        float a0, a1; upk2(s, a0, a1);
        g_part[(size_t)(b * TILES1 + blockIdx.x) * 576 + 512 + tid] = a0 + a1;
    }
}

// =====================================================================
// Two-stage deterministic tile reduce
// =====================================================================
__global__ void reduce1_kernel()
{
    const int b  = blockIdx.y;
    const int ch = blockIdx.x;       // 0..RCH-1
    const int e  = threadIdx.x;      // 0..575
    float s = 0.0f;
    const float* p = &g_part[((size_t)b * TILES1 + ch * TPC) * 576 + e];
    #pragma unroll 5
    for (int t = 0; t < TPC; t++) s += p[(size_t)t * 576];
    g_part2[(b * RCH + ch) * 576 + e] = s;
}

__global__ void reduce2_kernel()
{
    const int b = blockIdx.x;
    const int e = threadIdx.x;
    float s = 0.0f;
    const float* p = &g_part2[(size_t)(b * RCH) * 576 + e];
    #pragma unroll
    for (int c = 0; c < RCH; c++) s += p[(size_t)c * 576];
    g_stats[b * 576 + e] = (e < 512) ? s : (s + EPSV);
}

// =====================================================================
// Pass 2 (TP2=128): q=softplus(Wq@{high|low}+bq); norm; O; out=wo@O+bo
// smem (bytes, total 107008):
//   Wq  f32[64][64]  @0      (16384)
//   Wo  f32[64][64]  @16384  (16384)
//   Asp u64[512]     @32768  (4096)
//   Ksp u64[64]      @36864  (512)
//   Ns  f32[8][128]  @37376  (4096)
//   HQ  f32[64][128] @41472  (32768)   Hs, then aliased by Qs (acc in regs)
//   LO  f32[64][128] @74240  (32768)   Ls, then aliased by Os
// =====================================================================
__global__ void __launch_bounds__(NT, 2)
pass2_kernel(const float* __restrict__ high, const float* __restrict__ low,
             const float* __restrict__ wqh, const float* __restrict__ bqh,
             const float* __restrict__ wql, const float* __restrict__ bql,
             const float* __restrict__ wo,  const float* __restrict__ bo,
             float* __restrict__ out)
{
    extern __shared__ __align__(16) char smem[];
    float* Wq  = (float*)smem;
    float* Wo  = (float*)(smem + 16384);
    u64*   Asp = (u64*)(smem + 32768);
    u64*   Ksp = (u64*)(smem + 36864);
    float* Ns  = (float*)(smem + 37376);
    float* HQ  = (float*)(smem + 41472);
    float* LO  = (float*)(smem + 74240);

    const int tid = threadIdx.x;
    const int b   = blockIdx.y;
    const int px0 = blockIdx.x * TP2;

    // Stage weights [c][oc] f32: i = cH*512 + oc*8 + cL
    for (int i = tid; i < 4096; i += NT) {
        int oc = (i >> 3) & 63;
        int c  = (i & 7) | ((i >> 9) << 3);
        Wq[c * 64 + oc] = (oc < 32) ? wqh[oc * 64 + c] : wql[(oc - 32) * 64 + c];
        Wo[c * 64 + oc] = wo[oc * 64 + c];
    }
    // Stage input tiles
    for (int i = tid; i < 8192; i += NT) {
        int c = i >> 7, n = i & 127;
        size_t base = (size_t)(b * 64 + c) * HW + px0 + n;
        HQ[i] = high[base];
        LO[i] = low[base];
    }
    // Stage attn / ksum+eps packed
    { float a = g_stats[b * 576 + tid];                Asp[tid] = pk2(a, a); }
    if (tid < 64) { float k = g_stats[b * 576 + 512 + tid]; Ksp[tid] = pk2(k, k); }
    __syncthreads();

    const int cg = tid >> 5;        // 0..15
    const int pg = tid & 31;        // 0..31
    const int co = cg * 4;
    const int j0 = pg * 4;

    // ---- GEMM1: q = softplus(Wq @ {H|L} + b); accs stay in regs over barrier ----
    {
        const float* src = (co < 32) ? HQ : LO;
        u64 acc[4][2];
        #pragma unroll
        for (int i = 0; i < 4; i++) {
            int oc = co + i;
            float bi = (oc < 32) ? bqh[oc] : bql[oc - 32];
            u64 bp = pk2(bi, bi);
            acc[i][0] = bp; acc[i][1] = bp;
        }
        #pragma unroll 8
        for (int c = 0; c < 64; c++) {
            float4 wf = *(const float4*)&Wq[c * 64 + co];
            u64 w0 = pk2(wf.x, wf.x), w1 = pk2(wf.y, wf.y);
            u64 w2 = pk2(wf.z, wf.z), w3 = pk2(wf.w, wf.w);
            ulonglong2 x = *(const ulonglong2*)&src[c * 128 + j0];
            acc[0][0] = f2fma(w0, x.x, acc[0][0]); acc[0][1] = f2fma(w0, x.y, acc[0][1]);
            acc[1][0] = f2fma(w1, x.x, acc[1][0]); acc[1][1] = f2fma(w1, x.y, acc[1][1]);
            acc[2][0] = f2fma(w2, x.x, acc[2][0]); acc[2][1] = f2fma(w2, x.y, acc[2][1]);
            acc[3][0] = f2fma(w3, x.x, acc[3][0]); acc[3][1] = f2fma(w3, x.y, acc[3][1]);
        }

        __syncthreads();   // all reads of HQ done; safe to overwrite with Qs

        #pragma unroll
        for (int i = 0; i < 4; i++) {
            float v0, v1, v2, v3;
            upk2(acc[i][0], v0, v1);
            upk2(acc[i][1], v2, v3);
            v0 = softplusf(v0); v1 = softplusf(v1);
            v2 = softplusf(v2); v3 = softplusf(v3);
            *(float4*)&HQ[(co + i) * 128 + j0] = make_float4(v0, v1, v2, v3);
        }
    }
    __syncthreads();

    // ---- norm: 8 heads x 64 pixel-pairs ----
    {
        const int p  = tid >> 6;
        const int n2 = tid & 63;
        u64 s = 0ull;
        #pragma unroll
        for (int m = 0; m < 8; m++)
            s = f2fma(*(const u64*)&HQ[(p * 8 + m) * 128 + 2 * n2], Ksp[p * 8 + m], s);
        float d0, d1; upk2(s, d0, d1);
        *(u64*)&Ns[p * 128 + 2 * n2] = pk2(1.0f / d0, 1.0f / d1);
    }
    __syncthreads();

    // ---- stage A: O[ch][n] into LO (Ls no longer needed) ----
    #pragma unroll
    for (int it = 0; it < 8; it++) {
        int idx = it * NT + tid;          // 64 ch x 64 pairs
        int ch = idx >> 6, n2 = idx & 63;
        int p = ch >> 3, cc = ch & 7;
        u64 s = 0ull;
        #pragma unroll
        for (int m = 0; m < 8; m++)
            s = f2fma(*(const u64*)&HQ[(p * 8 + m) * 128 + 2 * n2],
                      Asp[p * 64 + m * 8 + cc], s);
        s = f2mul(s, *(const u64*)&Ns[p * 128 + 2 * n2]);
        *(u64*)&LO[ch * 128 + 2 * n2] = s;
    }
    __syncthreads();

    // ---- GEMM3: out = Wo @ O + bo ----
    {
        u64 acc[4][2];
        #pragma unroll
        for (int i = 0; i < 4; i++) {
            float bi = bo[co + i];
            u64 bp = pk2(bi, bi);
            acc[i][0] = bp; acc[i][1] = bp;
        }
        #pragma unroll 8
        for (int c = 0; c < 64; c++) {
            float4 wf = *(const float4*)&Wo[c * 64 + co];
            u64 w0 = pk2(wf.x, wf.x), w1 = pk2(wf.y, wf.y);
            u64 w2 = pk2(wf.z, wf.z), w3 = pk2(wf.w, wf.w);
            ulonglong2 x = *(const ulonglong2*)&LO[c * 128 + j0];
            acc[0][0] = f2fma(w0, x.x, acc[0][0]); acc[0][1] = f2fma(w0, x.y, acc[0][1]);
            acc[1][0] = f2fma(w1, x.x, acc[1][0]); acc[1][1] = f2fma(w1, x.y, acc[1][1]);
            acc[2][0] = f2fma(w2, x.x, acc[2][0]); acc[2][1] = f2fma(w2, x.y, acc[2][1]);
            acc[3][0] = f2fma(w3, x.x, acc[3][0]); acc[3][1] = f2fma(w3, x.y, acc[3][1]);
        }
        float* dst = out + (size_t)b * 64 * HW + px0;
        #pragma unroll
        for (int i = 0; i < 4; i++) {
            float v0,v1,v2,v3;
            upk2(acc[i][0], v0, v1); upk2(acc[i][1], v2, v3);
            *(float4*)&dst[(size_t)(co + i) * HW + j0] = make_float4(v0, v1, v2, v3);
        }
    }
}

// =====================================================================
extern "C" void kernel_launch(void* const* d_in, const int* in_sizes, int n_in,
                              void* d_out, int out_size)
{
    const float* high = (const float*)d_in[0];
    const float* low  = (const float*)d_in[1];
    const float* wqh  = (const float*)d_in[2];
    const float* bqh  = (const float*)d_in[3];
    const float* wql  = (const float*)d_in[4];
    const float* bql  = (const float*)d_in[5];
    const float* wk   = (const float*)d_in[6];
    const float* bk   = (const float*)d_in[7];
    const float* wv   = (const float*)d_in[8];
    const float* bv   = (const float*)d_in[9];
    const float* wo   = (const float*)d_in[10];
    const float* bo   = (const float*)d_in[11];
    float* out = (float*)d_out;

    cudaFuncSetAttribute(pass1_kernel, cudaFuncAttributeMaxDynamicSharedMemorySize, 81920);
    cudaFuncSetAttribute(pass2_kernel, cudaFuncAttributeMaxDynamicSharedMemorySize, 107008);

    pass1_kernel<<<dim3(TILES1, BB), NT, 81920>>>(low, wk, bk, wv, bv);
    reduce1_kernel<<<dim3(RCH, BB), 576>>>();
    reduce2_kernel<<<BB, 576>>>();
    pass2_kernel<<<dim3(TILES2, BB), NT, 107008>>>(high, low, wqh, bqh, wql, bql, wo, bo, out);
}